// round 8
// baseline (speedup 1.0000x reference)
#include <cuda_runtime.h>

// IWT (inverse Haar) — fixed shapes from setup_inputs():
//   x:   [B=8, 4*C=256, H=256, W=256] float32
//   out: [B=8, C=64, 2H=512, 2W=512] float32
//
// out[b,c,2h+p,2w+q] = 0.25 * ( LL +/- LH +/- HL +/- HH ) butterfly.
//
// R6 body (best: 160.7us, DRAM 80.7%), ONE change: block size 256 -> 512.

#define IWT_B  8
#define IWT_C  64
#define IWT_H  256
#define IWT_W  256
#define IWT_W4 (IWT_W / 4)          // 64 float4 per input row
#define IWT_HW4 (IWT_H * IWT_W4)    // float4 per (subband,channel) plane = 16384
#define IWT_OROW4 (2 * IWT_W / 4)   // 128 float4 per output row
#define IWT_TPB 512

__global__ void __launch_bounds__(IWT_TPB) iwt_kernel(const float4* __restrict__ x,
                                                      float4* __restrict__ y) {
    unsigned tid = blockIdx.x * (unsigned)IWT_TPB + threadIdx.x;

    unsigned wv = tid & (IWT_W4 - 1);        // float4 index within input row
    unsigned t1 = tid >> 6;
    unsigned h  = t1 & (IWT_H - 1);
    unsigned t2 = t1 >> 8;
    unsigned c  = t2 & (IWT_C - 1);
    unsigned b  = t2 >> 6;

    // Input: subband k plane at offset k*C*HW4 from base of batch b.
    unsigned base = (b * 4u * IWT_C + c) * IWT_HW4 + h * IWT_W4 + wv;
    float4 ll = __ldcs(&x[base]);
    float4 lh = __ldcs(&x[base + 1u * IWT_C * IWT_HW4]);
    float4 hl = __ldcs(&x[base + 2u * IWT_C * IWT_HW4]);
    float4 hh = __ldcs(&x[base + 3u * IWT_C * IWT_HW4]);

    float L[4]  = {ll.x, ll.y, ll.z, ll.w};
    float Lh[4] = {lh.x, lh.y, lh.z, lh.w};
    float Hl[4] = {hl.x, hl.y, hl.z, hl.w};
    float Hh[4] = {hh.x, hh.y, hh.z, hh.w};

    float r0[8], r1[8];
#pragma unroll
    for (int j = 0; j < 4; j++) {
        float s_pp = (L[j] + Lh[j]) * 0.25f;   // (LL+LH)/4
        float s_pm = (L[j] - Lh[j]) * 0.25f;   // (LL-LH)/4
        float t_pp = (Hl[j] + Hh[j]) * 0.25f;  // (HL+HH)/4
        float t_pm = (Hl[j] - Hh[j]) * 0.25f;  // (HL-HH)/4
        r0[2 * j + 0] = s_pp + t_pp;   // out[2h  ][2w  ]
        r0[2 * j + 1] = s_pp - t_pp;   // out[2h  ][2w+1]
        r1[2 * j + 0] = s_pm + t_pm;   // out[2h+1][2w  ]
        r1[2 * j + 1] = s_pm - t_pm;   // out[2h+1][2w+1]
    }

    // Output rows 2h and 2h+1, cols [8*wv, 8*wv+8) -> two float4 each.
    unsigned orow = ((b * IWT_C + c) * (2 * IWT_H) + 2 * h) * IWT_OROW4 + 2 * wv;
    __stcs(&y[orow + 0],             make_float4(r0[0], r0[1], r0[2], r0[3]));
    __stcs(&y[orow + 1],             make_float4(r0[4], r0[5], r0[6], r0[7]));
    __stcs(&y[orow + IWT_OROW4 + 0], make_float4(r1[0], r1[1], r1[2], r1[3]));
    __stcs(&y[orow + IWT_OROW4 + 1], make_float4(r1[4], r1[5], r1[6], r1[7]));
}

extern "C" void kernel_launch(void* const* d_in, const int* in_sizes, int n_in,
                              void* d_out, int out_size) {
    const float4* x = (const float4*)d_in[0];
    float4* y = (float4*)d_out;
    // total threads = B*C*H*W/4 = 8,388,608 -> 16384 blocks of 512
    unsigned total = IWT_B * IWT_C * IWT_H * IWT_W4;
    iwt_kernel<<<total / IWT_TPB, IWT_TPB>>>(x, y);
}

// round 11
// speedup vs baseline: 1.4036x; 1.4036x over previous
#include <cuda_runtime.h>

// IWT (inverse Haar) — fixed shapes from setup_inputs():
//   x:   [B=8, 4*C=256, H=256, W=256] float32
//   out: [B=8, C=64, 2H=512, 2W=512] float32
//
// out[b,c,2h+p,2w+q] = 0.25 * ( LL +/- LH +/- HL +/- HH ) butterfly.
//
// R6 body (best: 160.7us, DRAM 80.7% @ 256 TPB), ONE change: 256 -> 128 TPB.
// R8 showed 512 TPB tanks DRAM to 56% via L1tex queue burstiness; testing the
// opposite direction.

#define IWT_B  8
#define IWT_C  64
#define IWT_H  256
#define IWT_W  256
#define IWT_W4 (IWT_W / 4)          // 64 float4 per input row
#define IWT_HW4 (IWT_H * IWT_W4)    // float4 per (subband,channel) plane = 16384
#define IWT_OROW4 (2 * IWT_W / 4)   // 128 float4 per output row
#define IWT_TPB 128

__global__ void __launch_bounds__(IWT_TPB) iwt_kernel(const float4* __restrict__ x,
                                                      float4* __restrict__ y) {
    unsigned tid = blockIdx.x * (unsigned)IWT_TPB + threadIdx.x;

    unsigned wv = tid & (IWT_W4 - 1);        // float4 index within input row
    unsigned t1 = tid >> 6;
    unsigned h  = t1 & (IWT_H - 1);
    unsigned t2 = t1 >> 8;
    unsigned c  = t2 & (IWT_C - 1);
    unsigned b  = t2 >> 6;

    // Input: subband k plane at offset k*C*HW4 from base of batch b.
    unsigned base = (b * 4u * IWT_C + c) * IWT_HW4 + h * IWT_W4 + wv;
    float4 ll = __ldcs(&x[base]);
    float4 lh = __ldcs(&x[base + 1u * IWT_C * IWT_HW4]);
    float4 hl = __ldcs(&x[base + 2u * IWT_C * IWT_HW4]);
    float4 hh = __ldcs(&x[base + 3u * IWT_C * IWT_HW4]);

    float L[4]  = {ll.x, ll.y, ll.z, ll.w};
    float Lh[4] = {lh.x, lh.y, lh.z, lh.w};
    float Hl[4] = {hl.x, hl.y, hl.z, hl.w};
    float Hh[4] = {hh.x, hh.y, hh.z, hh.w};

    float r0[8], r1[8];
#pragma unroll
    for (int j = 0; j < 4; j++) {
        float s_pp = (L[j] + Lh[j]) * 0.25f;   // (LL+LH)/4
        float s_pm = (L[j] - Lh[j]) * 0.25f;   // (LL-LH)/4
        float t_pp = (Hl[j] + Hh[j]) * 0.25f;  // (HL+HH)/4
        float t_pm = (Hl[j] - Hh[j]) * 0.25f;  // (HL-HH)/4
        r0[2 * j + 0] = s_pp + t_pp;   // out[2h  ][2w  ]
        r0[2 * j + 1] = s_pp - t_pp;   // out[2h  ][2w+1]
        r1[2 * j + 0] = s_pm + t_pm;   // out[2h+1][2w  ]
        r1[2 * j + 1] = s_pm - t_pm;   // out[2h+1][2w+1]
    }

    // Output rows 2h and 2h+1, cols [8*wv, 8*wv+8) -> two float4 each.
    unsigned orow = ((b * IWT_C + c) * (2 * IWT_H) + 2 * h) * IWT_OROW4 + 2 * wv;
    __stcs(&y[orow + 0],             make_float4(r0[0], r0[1], r0[2], r0[3]));
    __stcs(&y[orow + 1],             make_float4(r0[4], r0[5], r0[6], r0[7]));
    __stcs(&y[orow + IWT_OROW4 + 0], make_float4(r1[0], r1[1], r1[2], r1[3]));
    __stcs(&y[orow + IWT_OROW4 + 1], make_float4(r1[4], r1[5], r1[6], r1[7]));
}

extern "C" void kernel_launch(void* const* d_in, const int* in_sizes, int n_in,
                              void* d_out, int out_size) {
    const float4* x = (const float4*)d_in[0];
    float4* y = (float4*)d_out;
    // total threads = B*C*H*W/4 = 8,388,608 -> 65536 blocks of 128
    unsigned total = IWT_B * IWT_C * IWT_H * IWT_W4;
    iwt_kernel<<<total / IWT_TPB, IWT_TPB>>>(x, y);
}

// round 12
// speedup vs baseline: 1.4439x; 1.0287x over previous
#include <cuda_runtime.h>

// IWT (inverse Haar) — fixed shapes from setup_inputs():
//   x:   [B=8, 4*C=256, H=256, W=256] float32
//   out: [B=8, C=64, 2H=512, 2W=512] float32
//
// out[b,c,2h+p,2w+q] = 0.25 * ( LL +/- LH +/- HL +/- HH ) butterfly.
//
// Dense-store mapping: each thread owns ONE float2 per subband (input w pair
// 2*w2, 2*w2+1) and produces exactly one contiguous float4 per output row.
// Consecutive lanes -> consecutive float4s, so every STG.128 is a dense
// 512B/warp full-sector write (vs the previous stride-2 pattern that doubled
// store wavefronts). Loads stay fully coalesced (256B/warp/subband).

#define IWT_B  8
#define IWT_C  64
#define IWT_H  256
#define IWT_W  256
#define IWT_W2 (IWT_W / 2)           // 128 float2 per input row
#define IWT_HW2 (IWT_H * IWT_W2)     // float2 per (subband,channel) plane = 32768
#define IWT_OROW4 (2 * IWT_W / 4)    // 128 float4 per output row
#define IWT_TOTAL2 (IWT_B * IWT_C * IWT_H * IWT_W2)  // 16,777,216 threads
#define IWT_TPB 128

__global__ void __launch_bounds__(IWT_TPB) iwt_kernel(const float2* __restrict__ x,
                                                      float4* __restrict__ y) {
    unsigned tid = blockIdx.x * (unsigned)IWT_TPB + threadIdx.x;

    unsigned w2 = tid & (IWT_W2 - 1);        // float2 index within input row
    unsigned t1 = tid >> 7;
    unsigned h  = t1 & (IWT_H - 1);
    unsigned t2 = t1 >> 8;
    unsigned c  = t2 & (IWT_C - 1);
    unsigned b  = t2 >> 6;

    const unsigned P = IWT_C * IWT_HW2;      // subband plane stride (float2)
    unsigned base = (b * 4u * IWT_C + c) * IWT_HW2 + h * IWT_W2 + w2;
    float2 ll = __ldcs(&x[base]);
    float2 lh = __ldcs(&x[base + 1u * P]);
    float2 hl = __ldcs(&x[base + 2u * P]);
    float2 hh = __ldcs(&x[base + 3u * P]);

    // j = 0 -> output cols 4*w2+0,1 ; j = 1 -> output cols 4*w2+2,3
    float s_pp0 = (ll.x + lh.x) * 0.25f;
    float s_pm0 = (ll.x - lh.x) * 0.25f;
    float t_pp0 = (hl.x + hh.x) * 0.25f;
    float t_pm0 = (hl.x - hh.x) * 0.25f;
    float s_pp1 = (ll.y + lh.y) * 0.25f;
    float s_pm1 = (ll.y - lh.y) * 0.25f;
    float t_pp1 = (hl.y + hh.y) * 0.25f;
    float t_pm1 = (hl.y - hh.y) * 0.25f;

    float4 row0 = make_float4(s_pp0 + t_pp0, s_pp0 - t_pp0,
                              s_pp1 + t_pp1, s_pp1 - t_pp1);
    float4 row1 = make_float4(s_pm0 + t_pm0, s_pm0 - t_pm0,
                              s_pm1 + t_pm1, s_pm1 - t_pm1);

    // Output float4 index within row = w2 (cols 4*w2 .. 4*w2+3). Dense stores.
    unsigned orow = ((b * IWT_C + c) * (2 * IWT_H) + 2 * h) * IWT_OROW4 + w2;
    __stcs(&y[orow], row0);
    __stcs(&y[orow + IWT_OROW4], row1);
}

extern "C" void kernel_launch(void* const* d_in, const int* in_sizes, int n_in,
                              void* d_out, int out_size) {
    const float2* x = (const float2*)d_in[0];
    float4* y = (float4*)d_out;
    // 16,777,216 threads -> 131072 blocks of 128
    iwt_kernel<<<IWT_TOTAL2 / IWT_TPB, IWT_TPB>>>(x, y);
}